// round 1
// baseline (speedup 1.0000x reference)
#include <cuda_runtime.h>

// ---------------- problem constants (shapes fixed by the dataset) ----------
constexpr int Bn = 4;
constexpr int Nn = 8192;
constexpr int Cc = 32;
constexpr int M2 = 8192;
constexpr int M3 = 4096;
constexpr int M4 = 2048;
constexpr int MM = 4096;

constexpr int QPB   = 64;    // queries per block
constexpr int PARTS = 4;     // threads per query (split the M loop)
constexpr int TILE  = 512;   // known points staged in smem per tile
constexpr int NT    = 256;   // QPB * PARTS
constexpr float BIG = 3.0e38f;

// ---------------- device scratch (no allocations allowed) ------------------
__device__ float  g_v[96];                 // v = w_cls @ w_fc
__device__ float4 g_pk2[Bn * M2];          // (x,y,z,||k||^2)
__device__ float  g_fv2[Bn * M2];          // feats . v_seg
__device__ float4 g_pk3[Bn * M3];
__device__ float  g_fv3[Bn * M3];
__device__ float4 g_pk4[Bn * M4];
__device__ float  g_fv4[Bn * M4];
__device__ float4 g_pkm[Bn * MM];          // match points (w = ||k||^2)

// ---------------- tiny precompute kernels ----------------------------------
__global__ void compute_v_kernel(const float* __restrict__ w_fc,
                                 const float* __restrict__ w_cls) {
    int j = threadIdx.x;
    if (j < 96) {
        float acc = 0.f;
#pragma unroll
        for (int k = 0; k < 64; k++) acc = fmaf(w_cls[k], w_fc[k * 96 + j], acc);
        g_v[j] = acc;
    }
}

__global__ void pack_feat_kernel(const float* __restrict__ known,
                                 const float* __restrict__ feats,
                                 int total, int which) {
    int i = blockIdx.x * blockDim.x + threadIdx.x;
    if (i >= total) return;
    float4* pk; float* fv; int voff;
    if (which == 0)      { pk = g_pk2; fv = g_fv2; voff = 0;  }
    else if (which == 1) { pk = g_pk3; fv = g_fv3; voff = 32; }
    else                 { pk = g_pk4; fv = g_fv4; voff = 64; }

    float x = known[3 * i + 0];
    float y = known[3 * i + 1];
    float z = known[3 * i + 2];
    // same rounding order as jnp.sum(known*known, -1): (x^2 + y^2) + z^2
    float kk = __fadd_rn(__fadd_rn(__fmul_rn(x, x), __fmul_rn(y, y)), __fmul_rn(z, z));
    pk[i] = make_float4(x, y, z, kk);

    float acc = 0.f;
    const float4* f4 = reinterpret_cast<const float4*>(feats + (size_t)i * Cc);
#pragma unroll
    for (int j = 0; j < 8; j++) {
        float4 t = f4[j];
        acc = fmaf(t.x, g_v[voff + 4 * j + 0], acc);
        acc = fmaf(t.y, g_v[voff + 4 * j + 1], acc);
        acc = fmaf(t.z, g_v[voff + 4 * j + 2], acc);
        acc = fmaf(t.w, g_v[voff + 4 * j + 3], acc);
    }
    fv[i] = acc;
}

__global__ void pack_match_kernel(const float* __restrict__ known, int total) {
    int i = blockIdx.x * blockDim.x + threadIdx.x;
    if (i >= total) return;
    float x = known[3 * i + 0];
    float y = known[3 * i + 1];
    float z = known[3 * i + 2];
    float kk = __fadd_rn(__fadd_rn(__fmul_rn(x, x), __fmul_rn(y, y)), __fmul_rn(z, z));
    g_pkm[i] = make_float4(x, y, z, kk);
}

// ---------------- top-3 maintenance -----------------------------------------
// caller guarantees d < t2 (keeps the hot path to a single compare+branch)
__device__ __forceinline__ void top3_insert(float d, float f,
                                            float& t0, float& t1, float& t2,
                                            float& f0, float& f1, float& f2) {
    if (d < t1) {
        t2 = t1; f2 = f1;
        if (d < t0) { t1 = t0; f1 = f0; t0 = d; f0 = f; }
        else        { t1 = d;  f1 = f; }
    } else { t2 = d; f2 = f; }
}

// one interpolation set: returns the pred contribution (valid only for part==0)
__device__ __forceinline__ float process_set(
    const float4* __restrict__ pk, const float* __restrict__ fvp, int M,
    float qq, float n2x, float n2y, float n2z,
    int tid, int part, int q,
    float4* s_e, float* s_f, float2* s_m)
{
    float t0 = BIG, t1 = BIG, t2 = BIG;
    float f0 = 0.f, f1 = 0.f, f2 = 0.f;

    for (int tb = 0; tb < M; tb += TILE) {
        __syncthreads();
#pragma unroll
        for (int i = tid; i < TILE; i += NT) {
            s_e[i] = pk[tb + i];
            s_f[i] = fvp[tb + i];
        }
        __syncthreads();
        const float4* ep = s_e + part * (TILE / PARTS);
        const float*  fp = s_f + part * (TILE / PARTS);
#pragma unroll 4
        for (int i = 0; i < TILE / PARTS; i++) {
            float4 e = ep[i];
            float d = fmaf(n2x, e.x, qq + e.w);
            d = fmaf(n2y, e.y, d);
            d = fmaf(n2z, e.z, d);
            if (d < t2) top3_insert(d, fp[i], t0, t1, t2, f0, f1, f2);
        }
    }

    __syncthreads();
    int mb = (q * PARTS + part) * 3;
    s_m[mb + 0] = make_float2(t0, f0);
    s_m[mb + 1] = make_float2(t1, f1);
    s_m[mb + 2] = make_float2(t2, f2);
    __syncthreads();

    float contrib = 0.f;
    if (part == 0) {
        float m0 = BIG, m1 = BIG, m2 = BIG;
        float h0 = 0.f, h1 = 0.f, h2 = 0.f;
#pragma unroll
        for (int j = 0; j < PARTS * 3; j++) {
            float2 c = s_m[q * PARTS * 3 + j];
            if (c.x < m2) top3_insert(c.x, c.y, m0, m1, m2, h0, h1, h2);
        }
        float d0 = fmaxf(m0, 0.f), d1 = fmaxf(m1, 0.f), d2c = fmaxf(m2, 0.f);
        float r0 = 1.f / (d0 + 1e-8f);
        float r1 = 1.f / (d1 + 1e-8f);
        float r2 = 1.f / (d2c + 1e-8f);
        contrib = fmaf(r0, h0, fmaf(r1, h1, r2 * h2)) / (r0 + r1 + r2);
    }
    __syncthreads();
    return contrib;
}

// min squared distance to match points (valid only for part==0)
__device__ __forceinline__ float process_min(
    const float4* __restrict__ pk, int M,
    float qq, float x, float y, float z,
    int tid, int part, int q,
    float4* s_e, float* s_min)
{
    float mn = BIG;
    for (int tb = 0; tb < M; tb += TILE) {
        __syncthreads();
#pragma unroll
        for (int i = tid; i < TILE; i += NT) s_e[i] = pk[tb + i];
        __syncthreads();
        const float4* ep = s_e + part * (TILE / PARTS);
#pragma unroll 4
        for (int i = 0; i < TILE / PARTS; i++) {
            float4 e = ep[i];
            // mimic reference rounding: (qq + kk) - 2*((x*mx + y*my) + z*mz)
            float dot = __fadd_rn(__fadd_rn(__fmul_rn(x, e.x), __fmul_rn(y, e.y)),
                                  __fmul_rn(z, e.z));
            float d = __fsub_rn(__fadd_rn(qq, e.w), __fadd_rn(dot, dot));
            mn = fminf(mn, d);
        }
    }
    __syncthreads();
    s_min[q * PARTS + part] = mn;
    __syncthreads();
    if (part == 0) {
        mn = fminf(fminf(s_min[q * 4 + 0], s_min[q * 4 + 1]),
                   fminf(s_min[q * 4 + 2], s_min[q * 4 + 3]));
    }
    return mn;
}

// ---------------- fused main kernel -----------------------------------------
__global__ void __launch_bounds__(NT)
fused_kernel(const float* __restrict__ pts, float* __restrict__ out) {
    __shared__ float4 s_e[TILE];
    __shared__ float  s_f[TILE];
    __shared__ float2 s_m[QPB * PARTS * 3];

    const int tid  = threadIdx.x;
    const int q    = tid & (QPB - 1);
    const int part = tid >> 6;
    const int gq   = blockIdx.x * QPB + q;   // flat query over B*N
    const int b    = gq >> 13;                // / Nn

    const float x = pts[3 * gq + 0];
    const float y = pts[3 * gq + 1];
    const float z = pts[3 * gq + 2];
    const float qq = __fadd_rn(__fadd_rn(__fmul_rn(x, x), __fmul_rn(y, y)),
                               __fmul_rn(z, z));
    const float n2x = -2.f * x, n2y = -2.f * y, n2z = -2.f * z;

    float pred;
    pred  = process_set(g_pk2 + b * M2, g_fv2 + b * M2, M2, qq, n2x, n2y, n2z,
                        tid, part, q, s_e, s_f, s_m);
    pred += process_set(g_pk3 + b * M3, g_fv3 + b * M3, M3, qq, n2x, n2y, n2z,
                        tid, part, q, s_e, s_f, s_m);
    pred += process_set(g_pk4 + b * M4, g_fv4 + b * M4, M4, qq, n2x, n2y, n2z,
                        tid, part, q, s_e, s_f, s_m);
    float mn = process_min(g_pkm + b * MM, MM, qq, x, y, z,
                           tid, part, q, s_e, reinterpret_cast<float*>(s_m));

    if (part == 0) {
        out[gq] = pred;                                      // pred_hm (B,N,1)
        out[Bn * Nn + gq] = (fmaxf(mn, 0.f) < 0.25f) ? 1.0f : 0.0f;  // gt_hm
    }
}

// ---------------- launch ----------------------------------------------------
extern "C" void kernel_launch(void* const* d_in, const int* in_sizes, int n_in,
                              void* d_out, int out_size) {
    (void)in_sizes; (void)n_in; (void)out_size;
    const float* pts    = (const float*)d_in[0];
    const float* known2 = (const float*)d_in[1];
    const float* feats2 = (const float*)d_in[2];
    const float* known3 = (const float*)d_in[3];
    const float* feats3 = (const float*)d_in[4];
    const float* known4 = (const float*)d_in[5];
    const float* feats4 = (const float*)d_in[6];
    const float* matchp = (const float*)d_in[7];
    const float* w_fc   = (const float*)d_in[8];
    const float* w_cls  = (const float*)d_in[9];
    float* out = (float*)d_out;

    compute_v_kernel<<<1, 96>>>(w_fc, w_cls);
    pack_feat_kernel<<<(Bn * M2 + 255) / 256, 256>>>(known2, feats2, Bn * M2, 0);
    pack_feat_kernel<<<(Bn * M3 + 255) / 256, 256>>>(known3, feats3, Bn * M3, 1);
    pack_feat_kernel<<<(Bn * M4 + 255) / 256, 256>>>(known4, feats4, Bn * M4, 2);
    pack_match_kernel<<<(Bn * MM + 255) / 256, 256>>>(matchp, Bn * MM);
    fused_kernel<<<(Bn * Nn) / QPB, NT>>>(pts, out);
}

// round 2
// speedup vs baseline: 1.0016x; 1.0016x over previous
#include <cuda_runtime.h>

// ---------------- problem constants (shapes fixed by the dataset) ----------
constexpr int Bn = 4;
constexpr int Nn = 8192;
constexpr int Cc = 32;
constexpr int M2 = 8192;
constexpr int M3 = 4096;
constexpr int M4 = 2048;
constexpr int MM = 4096;

constexpr int QPB   = 64;    // queries per block
constexpr int PARTS = 4;     // threads per query (split the M loop)
constexpr int TILE  = 512;   // known points staged in smem per tile
constexpr int NT    = 256;   // QPB * PARTS
constexpr float BIG = 3.0e38f;

// ---------------- device scratch (no allocations allowed) ------------------
__device__ float  g_v[96];                 // v = w_cls @ w_fc
__device__ float4 g_pk2[Bn * M2];          // (x,y,z,||k||^2)
__device__ float  g_fv2[Bn * M2];          // feats . v_seg
__device__ float4 g_pk3[Bn * M3];
__device__ float  g_fv3[Bn * M3];
__device__ float4 g_pk4[Bn * M4];
__device__ float  g_fv4[Bn * M4];
__device__ float4 g_pkm[Bn * MM];          // match points (w = ||k||^2)

// ---------------- tiny precompute kernels ----------------------------------
__global__ void compute_v_kernel(const float* __restrict__ w_fc,
                                 const float* __restrict__ w_cls) {
    int j = threadIdx.x;
    if (j < 96) {
        float acc = 0.f;
#pragma unroll
        for (int k = 0; k < 64; k++) acc = fmaf(w_cls[k], w_fc[k * 96 + j], acc);
        g_v[j] = acc;
    }
}

__global__ void pack_feat_kernel(const float* __restrict__ known,
                                 const float* __restrict__ feats,
                                 int total, int which) {
    int i = blockIdx.x * blockDim.x + threadIdx.x;
    if (i >= total) return;
    float4* pk; float* fv; int voff;
    if (which == 0)      { pk = g_pk2; fv = g_fv2; voff = 0;  }
    else if (which == 1) { pk = g_pk3; fv = g_fv3; voff = 32; }
    else                 { pk = g_pk4; fv = g_fv4; voff = 64; }

    float x = known[3 * i + 0];
    float y = known[3 * i + 1];
    float z = known[3 * i + 2];
    // same rounding order as jnp.sum(known*known, -1): (x^2 + y^2) + z^2
    float kk = __fadd_rn(__fadd_rn(__fmul_rn(x, x), __fmul_rn(y, y)), __fmul_rn(z, z));
    pk[i] = make_float4(x, y, z, kk);

    float acc = 0.f;
    const float4* f4 = reinterpret_cast<const float4*>(feats + (size_t)i * Cc);
#pragma unroll
    for (int j = 0; j < 8; j++) {
        float4 t = f4[j];
        acc = fmaf(t.x, g_v[voff + 4 * j + 0], acc);
        acc = fmaf(t.y, g_v[voff + 4 * j + 1], acc);
        acc = fmaf(t.z, g_v[voff + 4 * j + 2], acc);
        acc = fmaf(t.w, g_v[voff + 4 * j + 3], acc);
    }
    fv[i] = acc;
}

__global__ void pack_match_kernel(const float* __restrict__ known, int total) {
    int i = blockIdx.x * blockDim.x + threadIdx.x;
    if (i >= total) return;
    float x = known[3 * i + 0];
    float y = known[3 * i + 1];
    float z = known[3 * i + 2];
    float kk = __fadd_rn(__fadd_rn(__fmul_rn(x, x), __fmul_rn(y, y)), __fmul_rn(z, z));
    g_pkm[i] = make_float4(x, y, z, kk);
}

// ---------------- top-3 maintenance -----------------------------------------
// caller guarantees d < t2 (keeps the hot path to a single compare+branch)
__device__ __forceinline__ void top3_insert(float d, float f,
                                            float& t0, float& t1, float& t2,
                                            float& f0, float& f1, float& f2) {
    if (d < t1) {
        t2 = t1; f2 = f1;
        if (d < t0) { t1 = t0; f1 = f0; t0 = d; f0 = f; }
        else        { t1 = d;  f1 = f; }
    } else { t2 = d; f2 = f; }
}

// one interpolation set: returns the pred contribution (valid only for part==0)
__device__ __forceinline__ float process_set(
    const float4* __restrict__ pk, const float* __restrict__ fvp, int M,
    float qq, float n2x, float n2y, float n2z,
    int tid, int part, int q,
    float4* s_e, float* s_f, float2* s_m)
{
    float t0 = BIG, t1 = BIG, t2 = BIG;
    float f0 = 0.f, f1 = 0.f, f2 = 0.f;

    for (int tb = 0; tb < M; tb += TILE) {
        __syncthreads();
#pragma unroll
        for (int i = tid; i < TILE; i += NT) {
            s_e[i] = pk[tb + i];
            s_f[i] = fvp[tb + i];
        }
        __syncthreads();
        const float4* ep = s_e + part * (TILE / PARTS);
        const float*  fp = s_f + part * (TILE / PARTS);
#pragma unroll 4
        for (int i = 0; i < TILE / PARTS; i++) {
            float4 e = ep[i];
            float d = fmaf(n2x, e.x, qq + e.w);
            d = fmaf(n2y, e.y, d);
            d = fmaf(n2z, e.z, d);
            if (d < t2) top3_insert(d, fp[i], t0, t1, t2, f0, f1, f2);
        }
    }

    __syncthreads();
    int mb = (q * PARTS + part) * 3;
    s_m[mb + 0] = make_float2(t0, f0);
    s_m[mb + 1] = make_float2(t1, f1);
    s_m[mb + 2] = make_float2(t2, f2);
    __syncthreads();

    float contrib = 0.f;
    if (part == 0) {
        float m0 = BIG, m1 = BIG, m2 = BIG;
        float h0 = 0.f, h1 = 0.f, h2 = 0.f;
#pragma unroll
        for (int j = 0; j < PARTS * 3; j++) {
            float2 c = s_m[q * PARTS * 3 + j];
            if (c.x < m2) top3_insert(c.x, c.y, m0, m1, m2, h0, h1, h2);
        }
        float d0 = fmaxf(m0, 0.f), d1 = fmaxf(m1, 0.f), d2c = fmaxf(m2, 0.f);
        float r0 = 1.f / (d0 + 1e-8f);
        float r1 = 1.f / (d1 + 1e-8f);
        float r2 = 1.f / (d2c + 1e-8f);
        contrib = fmaf(r0, h0, fmaf(r1, h1, r2 * h2)) / (r0 + r1 + r2);
    }
    __syncthreads();
    return contrib;
}

// min squared distance to match points (valid only for part==0)
__device__ __forceinline__ float process_min(
    const float4* __restrict__ pk, int M,
    float qq, float x, float y, float z,
    int tid, int part, int q,
    float4* s_e, float* s_min)
{
    float mn = BIG;
    for (int tb = 0; tb < M; tb += TILE) {
        __syncthreads();
#pragma unroll
        for (int i = tid; i < TILE; i += NT) s_e[i] = pk[tb + i];
        __syncthreads();
        const float4* ep = s_e + part * (TILE / PARTS);
#pragma unroll 4
        for (int i = 0; i < TILE / PARTS; i++) {
            float4 e = ep[i];
            // mimic reference rounding: (qq + kk) - 2*((x*mx + y*my) + z*mz)
            float dot = __fadd_rn(__fadd_rn(__fmul_rn(x, e.x), __fmul_rn(y, e.y)),
                                  __fmul_rn(z, e.z));
            float d = __fsub_rn(__fadd_rn(qq, e.w), __fadd_rn(dot, dot));
            mn = fminf(mn, d);
        }
    }
    __syncthreads();
    s_min[q * PARTS + part] = mn;
    __syncthreads();
    if (part == 0) {
        mn = fminf(fminf(s_min[q * 4 + 0], s_min[q * 4 + 1]),
                   fminf(s_min[q * 4 + 2], s_min[q * 4 + 3]));
    }
    return mn;
}

// ---------------- fused main kernel -----------------------------------------
__global__ void __launch_bounds__(NT)
fused_kernel(const float* __restrict__ pts, float* __restrict__ out) {
    __shared__ float4 s_e[TILE];
    __shared__ float  s_f[TILE];
    __shared__ float2 s_m[QPB * PARTS * 3];

    const int tid  = threadIdx.x;
    const int q    = tid & (QPB - 1);
    const int part = tid >> 6;
    const int gq   = blockIdx.x * QPB + q;   // flat query over B*N
    const int b    = gq >> 13;                // / Nn

    const float x = pts[3 * gq + 0];
    const float y = pts[3 * gq + 1];
    const float z = pts[3 * gq + 2];
    const float qq = __fadd_rn(__fadd_rn(__fmul_rn(x, x), __fmul_rn(y, y)),
                               __fmul_rn(z, z));
    const float n2x = -2.f * x, n2y = -2.f * y, n2z = -2.f * z;

    float pred;
    pred  = process_set(g_pk2 + b * M2, g_fv2 + b * M2, M2, qq, n2x, n2y, n2z,
                        tid, part, q, s_e, s_f, s_m);
    pred += process_set(g_pk3 + b * M3, g_fv3 + b * M3, M3, qq, n2x, n2y, n2z,
                        tid, part, q, s_e, s_f, s_m);
    pred += process_set(g_pk4 + b * M4, g_fv4 + b * M4, M4, qq, n2x, n2y, n2z,
                        tid, part, q, s_e, s_f, s_m);
    float mn = process_min(g_pkm + b * MM, MM, qq, x, y, z,
                           tid, part, q, s_e, reinterpret_cast<float*>(s_m));

    if (part == 0) {
        out[gq] = pred;                                      // pred_hm (B,N,1)
        out[Bn * Nn + gq] = (fmaxf(mn, 0.f) < 0.25f) ? 1.0f : 0.0f;  // gt_hm
    }
}

// ---------------- launch ----------------------------------------------------
extern "C" void kernel_launch(void* const* d_in, const int* in_sizes, int n_in,
                              void* d_out, int out_size) {
    (void)in_sizes; (void)n_in; (void)out_size;
    const float* pts    = (const float*)d_in[0];
    const float* known2 = (const float*)d_in[1];
    const float* feats2 = (const float*)d_in[2];
    const float* known3 = (const float*)d_in[3];
    const float* feats3 = (const float*)d_in[4];
    const float* known4 = (const float*)d_in[5];
    const float* feats4 = (const float*)d_in[6];
    const float* matchp = (const float*)d_in[7];
    const float* w_fc   = (const float*)d_in[8];
    const float* w_cls  = (const float*)d_in[9];
    float* out = (float*)d_out;

    compute_v_kernel<<<1, 96>>>(w_fc, w_cls);
    pack_feat_kernel<<<(Bn * M2 + 255) / 256, 256>>>(known2, feats2, Bn * M2, 0);
    pack_feat_kernel<<<(Bn * M3 + 255) / 256, 256>>>(known3, feats3, Bn * M3, 1);
    pack_feat_kernel<<<(Bn * M4 + 255) / 256, 256>>>(known4, feats4, Bn * M4, 2);
    pack_match_kernel<<<(Bn * MM + 255) / 256, 256>>>(matchp, Bn * MM);
    fused_kernel<<<(Bn * Nn) / QPB, NT>>>(pts, out);
}